// round 2
// baseline (speedup 1.0000x reference)
#include <cuda_runtime.h>
#include <cstdint>

namespace {
constexpr int kB  = 16384;
constexpr int kT  = 79;
constexpr int kH  = 256;
constexpr int kD  = 256;
constexpr int kBM = 128;            // batch rows per CTA
constexpr int kTH = 512;            // threads per CTA (16 warps)
constexpr int kKC = 16;             // k-rows per U chunk
constexpr int kNC = kH / kKC;       // 16 chunks per step

// shared memory layout (bytes)
constexpr int HT_OFF  = 0;                         // hT: [256][128] f32 (transposed h)
constexpr int HT_BY   = kH * kBM * 4;              // 131072
constexpr int UB_OFF  = HT_OFF + HT_BY;            // 2 x duplicated U chunk [16][512]
constexpr int UB_BY   = kKC * 2 * kH * 4;          // 32768
constexpr int WIN_OFF = UB_OFF + 2 * UB_BY;        // duplicated W_in [3][512]
constexpr int BR_OFF  = WIN_OFF + 3 * 2 * kH * 4;  // duplicated b_rnn [512]
constexpr int BD_OFF  = BR_OFF + 2 * kH * 4;       // duplicated b_d   [512]
constexpr int SMEM_BY = BD_OFF + 2 * kH * 4;       // 206848 bytes
}

// ---- packed f32x2 helpers ----
__device__ __forceinline__ void fma2(unsigned long long& c,
                                     unsigned long long a,
                                     unsigned long long b) {
    asm("fma.rn.f32x2 %0, %1, %2, %0;" : "+l"(c) : "l"(a), "l"(b));
}
__device__ __forceinline__ unsigned long long pack2(float lo, float hi) {
    unsigned long long r;
    asm("mov.b64 %0, {%1, %2};" : "=l"(r) : "f"(lo), "f"(hi));
    return r;
}
__device__ __forceinline__ void unpack2(unsigned long long p, float& lo, float& hi) {
    asm("mov.b64 {%0, %1}, %2;" : "=f"(lo), "=f"(hi) : "l"(p));
}
__device__ __forceinline__ void lds2(uint32_t a, unsigned long long& p0, unsigned long long& p1) {
    asm volatile("ld.shared.v2.b64 {%0, %1}, [%2];" : "=l"(p0), "=l"(p1) : "r"(a));
}
__device__ __forceinline__ void sts4(uint32_t a, float v0, float v1, float v2, float v3) {
    asm volatile("st.shared.v4.f32 [%0], {%1, %2, %3, %4};"
                 :: "r"(a), "f"(v0), "f"(v1), "f"(v2), "f"(v3));
}

// Fused reversed-input RNN:
//   hT_sm[k][i] holds h transposed; per step: h = relu(x_t W_in + b_rnn + h U)
//   computed as hT_new[j][i] = relu(proj[j][i] + sum_k U[k][j] * hT[k][i])
// Thread tile: warp w -> j in [16w, 16w+16); lane L -> i in [4L, 4L+4).
// Accumulators are f32x2 pairs along i: A pairs load directly from hT rows,
// B (U row) is stored duplicated in smem so b-pairs load directly too.
__global__ void __launch_bounds__(kTH, 1)
rnn_fused_kernel(const float* __restrict__ x0, const float* __restrict__ x1,
                 const float* __restrict__ x2, const float* __restrict__ Win,
                 const float* __restrict__ U,  const float* __restrict__ brnn,
                 const float* __restrict__ Wd, const float* __restrict__ bd,
                 float* __restrict__ out) {
    extern __shared__ float smemf[];
    const uint32_t sb = (uint32_t)__cvta_generic_to_shared(smemf);

    const int tid = threadIdx.x;
    const int w   = tid >> 5;
    const int L   = tid & 31;
    const int j0  = w * 16;
    const int i0  = L * 4;
    const int b0  = blockIdx.x * kBM;

    // ---- stage duplicated W_in, b_rnn, b_d ----
    for (int idx = tid; idx < 3 * kH; idx += kTH) {
        const int f = idx >> 8, h = idx & 255;
        const float v = Win[f * kH + h];
        smemf[WIN_OFF / 4 + f * 512 + 2 * h]     = v;
        smemf[WIN_OFF / 4 + f * 512 + 2 * h + 1] = v;
    }
    for (int h = tid; h < kH; h += kTH) {
        const float vb = brnn[h];
        smemf[BR_OFF / 4 + 2 * h] = vb; smemf[BR_OFF / 4 + 2 * h + 1] = vb;
        const float vd = bd[h];
        smemf[BD_OFF / 4 + 2 * h] = vd; smemf[BD_OFF / 4 + 2 * h + 1] = vd;
    }
    __syncthreads();

    unsigned long long acc[16][2];
    float2 sreg[4];

    // acc[j][ip] = x0[i]*W_in[0][j] + x1[i]*W_in[1][j] + x2[i]*W_in[2][j] + b_rnn[j]
    auto init_proj = [&](int rt) {
        float a0v[4], a1v[4], a2v[4];
        #pragma unroll
        for (int c = 0; c < 4; c++) {
            const int ofs = (b0 + i0 + c) * kT + rt;
            a0v[c] = __ldg(x0 + ofs);
            a1v[c] = __ldg(x1 + ofs);
            a2v[c] = __ldg(x2 + ofs);
        }
        const unsigned long long xp0[2] = {pack2(a0v[0], a0v[1]), pack2(a0v[2], a0v[3])};
        const unsigned long long xp1[2] = {pack2(a1v[0], a1v[1]), pack2(a1v[2], a1v[3])};
        const unsigned long long xp2[2] = {pack2(a2v[0], a2v[1]), pack2(a2v[2], a2v[3])};
        const uint32_t wb = sb + WIN_OFF + j0 * 8;
        const uint32_t bb = sb + BR_OFF + j0 * 8;
        #pragma unroll
        for (int q = 0; q < 16; q += 2) {
            unsigned long long w0a, w0b, w1a, w1b, w2a, w2b, ba, bbp;
            lds2(bb + q * 8, ba, bbp);
            lds2(wb + q * 8, w0a, w0b);
            lds2(wb + 2048 + q * 8, w1a, w1b);
            lds2(wb + 4096 + q * 8, w2a, w2b);
            #pragma unroll
            for (int ip = 0; ip < 2; ip++) {
                unsigned long long t0 = ba;
                fma2(t0, xp0[ip], w0a); fma2(t0, xp1[ip], w1a); fma2(t0, xp2[ip], w2a);
                acc[q][ip] = t0;
                unsigned long long t1 = bbp;
                fma2(t1, xp0[ip], w0b); fma2(t1, xp1[ip], w1b); fma2(t1, xp2[ip], w2b);
                acc[q + 1][ip] = t1;
            }
        }
    };

    // GEMM over one k-chunk: reads hT rows (broadcast) and duplicated U rows
    auto gemm_chunk = [&](int buf, int c) {
        const uint32_t ab    = sb + HT_OFF + c * kKC * 512 + L * 16;
        const uint32_t bbase = sb + UB_OFF + buf * UB_BY + j0 * 8;
        #pragma unroll
        for (int kk = 0; kk < kKC; kk++) {
            unsigned long long a0, a1, bp[16];
            lds2(ab + kk * 512, a0, a1);
            #pragma unroll
            for (int q = 0; q < 16; q += 2)
                lds2(bbase + kk * 2048 + q * 8, bp[q], bp[q + 1]);
            #pragma unroll
            for (int q = 0; q < 16; q++) {
                fma2(acc[q][0], a0, bp[q]);
                fma2(acc[q][1], a1, bp[q]);
            }
        }
    };

    // stream a 16-row chunk of a [256x256] weight into regs, then dup-store to smem
    auto stage_load = [&](const float* src, int chunk) {
        const float2* s2 = reinterpret_cast<const float2*>(src + chunk * kKC * kH) + w * 128 + L;
        #pragma unroll
        for (int s = 0; s < 4; s++) sreg[s] = __ldg(s2 + 32 * s);
    };
    auto stage_store = [&](int buf) {
        const uint32_t db = sb + UB_OFF + buf * UB_BY + w * 2048 + L * 16;
        #pragma unroll
        for (int s = 0; s < 4; s++)
            sts4(db + s * 512, sreg[s].x, sreg[s].x, sreg[s].y, sreg[s].y);
    };

    auto writeback_relu = [&]() {
        #pragma unroll
        for (int q = 0; q < 16; q++) {
            float v0, v1, v2, v3;
            unpack2(acc[q][0], v0, v1);
            unpack2(acc[q][1], v2, v3);
            v0 = fmaxf(v0, 0.f); v1 = fmaxf(v1, 0.f);
            v2 = fmaxf(v2, 0.f); v3 = fmaxf(v3, 0.f);
            sts4(sb + HT_OFF + (j0 + q) * 512 + L * 16, v0, v1, v2, v3);
        }
    };

    // ---- t = 0: h = relu(proj) ----
    init_proj(kT - 1);
    writeback_relu();
    stage_load(U, 0);
    stage_store(0);
    __syncthreads();

    // ---- t = 1 .. 78 ----
    #pragma unroll 1
    for (int t = 1; t < kT; t++) {
        init_proj(kT - 1 - t);
        #pragma unroll 1
        for (int c = 0; c < kNC; c++) {
            const float* nsrc = (c + 1 < kNC) ? U : ((t + 1 < kT) ? U : Wd);
            stage_load(nsrc, (c + 1) & (kNC - 1));
            gemm_chunk(c & 1, c);
            __syncthreads();
            stage_store((c + 1) & 1);
            __syncthreads();
        }
        writeback_relu();
        __syncthreads();
    }

    // ---- epilogue: out = hT @ W_d + b_d ----
    {
        const uint32_t bb = sb + BD_OFF + j0 * 8;
        #pragma unroll
        for (int q = 0; q < 16; q += 2) {
            unsigned long long p0, p1;
            lds2(bb + q * 8, p0, p1);
            acc[q][0] = p0;     acc[q][1] = p0;
            acc[q + 1][0] = p1; acc[q + 1][1] = p1;
        }
        #pragma unroll 1
        for (int c = 0; c < kNC; c++) {
            if (c + 1 < kNC) stage_load(Wd, c + 1);
            gemm_chunk(c & 1, c);
            if (c + 1 < kNC) {
                __syncthreads();
                stage_store((c + 1) & 1);
                __syncthreads();
            }
        }
        #pragma unroll
        for (int q = 0; q < 16; q++) {
            float v0, v1, v2, v3;
            unpack2(acc[q][0], v0, v1);
            unpack2(acc[q][1], v2, v3);
            float* op = out + (b0 + i0) * kD + (j0 + q);
            op[0]      = v0;
            op[kD]     = v1;
            op[2 * kD] = v2;
            op[3 * kD] = v3;
        }
    }
}

extern "C" void kernel_launch(void* const* d_in, const int* in_sizes, int n_in,
                              void* d_out, int out_size) {
    const float* x0   = (const float*)d_in[0];
    const float* x1   = (const float*)d_in[1];
    const float* x2   = (const float*)d_in[2];
    const float* Win  = (const float*)d_in[3];
    const float* U    = (const float*)d_in[4];
    const float* brnn = (const float*)d_in[5];
    const float* Wd   = (const float*)d_in[6];
    const float* bd   = (const float*)d_in[7];
    float* out = (float*)d_out;

    cudaFuncSetAttribute(rnn_fused_kernel,
                         cudaFuncAttributeMaxDynamicSharedMemorySize, SMEM_BY);
    rnn_fused_kernel<<<kB / kBM, kTH, SMEM_BY>>>(x0, x1, x2, Win, U, brnn, Wd, bd, out);
}